// round 1
// baseline (speedup 1.0000x reference)
#include <cuda_runtime.h>
#include <cstdint>
#include <math.h>

// ---------------- problem constants ----------------
#define D_MODEL 64
#define HID     128
#define NRULES  4
#define K1      192              // 3*D_MODEL
#define BB      32
#define TT      8192
#define NTOK    (BB*TT)          // 262144
#define TILE    64               // tokens per block
#define NBLK    (NTOK/TILE)      // 4096
#define LN_EPS  1e-5f

// ---------------- smem layout (floats) ----------------
#define OFF_X   0
#define SZ_X    (66*64)          // halo tile: tokens t0-1 .. t0+64
#define OFF_W1  (OFF_X + SZ_X)
#define SZ_W1   (K1*HID)         // 192x128
#define OFF_W2  (OFF_W1 + SZ_W1)
#define SZ_W2   (HID*D_MODEL)    // 128x64
#define HPITCH  132              // padded pitch for h (bank-conflict-free)
#define OFF_H   (OFF_W2 + SZ_W2)
#define SZ_H    (64*HPITCH)
#define OFF_B1  (OFF_H + SZ_H)
#define OFF_B2  (OFF_B1 + HID)
#define SMEM_FLOATS (OFF_B2 + D_MODEL)
#define SMEM_BYTES  (SMEM_FLOATS*4)   // 182528 B

// ---------------- device state (no allocations allowed) ----------------
__device__ float g_rw[4];
__device__ float g_alpha;
__device__ int   g_nev;
__device__ float g_buf0[(size_t)NTOK*D_MODEL];
__device__ float g_buf1[(size_t)NTOK*D_MODEL];

// ---------------- packed f32x2 helpers (full-rate FMA on sm_10x) ----------------
typedef unsigned long long ull;

__device__ __forceinline__ ull fma2(ull a, ull b, ull c){
    ull d; asm("fma.rn.f32x2 %0, %1, %2, %3;" : "=l"(d) : "l"(a), "l"(b), "l"(c)); return d;
}
__device__ __forceinline__ ull dup2(float a){
    ull d; asm("mov.b64 %0, {%1, %2};" : "=l"(d) : "f"(a), "f"(a)); return d;
}
__device__ __forceinline__ float2 unp2(ull v){
    float2 r; asm("mov.b64 {%0, %1}, %2;" : "=f"(r.x), "=f"(r.y) : "l"(v)); return r;
}

__device__ __forceinline__ float gelu_exact(float x){
    return 0.5f * x * (1.0f + erff(x * 0.7071067811865475f));
}

// ---------------- control kernel: rule_weights, n_evolve, alpha ----------------
__global__ void control_kernel(
    const float* __restrict__ c,
    const float* __restrict__ p_sw1, const float* __restrict__ p_sb1,
    const float* __restrict__ p_sw2, const float* __restrict__ p_sb2,
    const float* __restrict__ p_tw1, const float* __restrict__ p_tb1,
    const float* __restrict__ p_tw2, const float* __restrict__ p_tb2,
    const float* __restrict__ p_rw1, const float* __restrict__ p_rb1,
    const float* __restrict__ p_rw2, const float* __restrict__ p_rb2)
{
    __shared__ float cs[128];
    __shared__ float h1[64];
    __shared__ float h2[32];
    __shared__ float h3[32];
    int t = threadIdx.x;
    if (t < 128) cs[t] = c[t];
    __syncthreads();

    if (t < 64){
        float a = p_sb1[t];
        for (int k = 0; k < 128; k++) a += cs[k] * p_sw1[k*64 + t];
        h1[t] = gelu_exact(a);
    } else if (t < 96){
        int i = t - 64;
        float a = p_tb1[i];
        for (int k = 0; k < 128; k++) a += cs[k] * p_tw1[k*32 + i];
        h2[i] = gelu_exact(a);
    } else {
        int i = t - 96;
        float a = p_rb1[i];
        for (int k = 0; k < 128; k++) a += cs[k] * p_rw1[k*32 + i];
        h3[i] = gelu_exact(a);
    }
    __syncthreads();

    if (t == 0){
        // rule selector softmax (4 logits)
        float l[4]; float mx = -1e30f;
        for (int r = 0; r < 4; r++){
            float a = p_sb2[r];
            for (int i = 0; i < 64; i++) a += h1[i] * p_sw2[i*4 + r];
            l[r] = a; mx = fmaxf(mx, a);
        }
        float s = 0.0f;
        for (int r = 0; r < 4; r++){ l[r] = expf(l[r] - mx); s += l[r]; }
        for (int r = 0; r < 4; r++) g_rw[r] = l[r] / s;
    }
    if (t == 1){
        // steps softmax (7 logits) -> n_evolve
        float l[7]; float mx = -1e30f;
        for (int j = 0; j < 7; j++){
            float a = p_tb2[j];
            for (int i = 0; i < 32; i++) a += h2[i] * p_tw2[i*7 + j];
            l[j] = a; mx = fmaxf(mx, a);
        }
        float s = 0.0f;
        for (int j = 0; j < 7; j++){ l[j] = expf(l[j] - mx); s += l[j]; }
        const float steps[7] = {2.0f,3.0f,4.0f,5.0f,6.0f,7.0f,8.0f};
        float nf = 0.0f;
        for (int j = 0; j < 7; j++) nf += (l[j] / s) * steps[j];
        int n = (int)(nf + 0.5f);           // trunc of positive == floor(x+0.5)
        if (n < 2) n = 2;
        if (n > 8) n = 8;
        g_nev = n;
    }
    if (t == 2){
        // residual gate alpha
        float v = p_rb2[0];
        for (int i = 0; i < 32; i++) v += h3[i] * p_rw2[i];
        g_alpha = 0.1f + 0.8f / (1.0f + expf(-v));
    }
}

// ---------------- evolve step ----------------
__global__ void __launch_bounds__(256, 1)
step_kernel(const float* __restrict__ cells_in,
            const float* __restrict__ rw1, const float* __restrict__ rb1,
            const float* __restrict__ rw2, const float* __restrict__ rb2,
            int j)
{
    if (j >= g_nev) return;

    extern __shared__ float sm[];
    float* x_s  = sm + OFF_X;
    float* w1s  = sm + OFF_W1;
    float* w2s  = sm + OFF_W2;
    float* h_s  = sm + OFF_H;
    float* b1s  = sm + OFF_B1;
    float* b2s  = sm + OFF_B2;
    __shared__ float rw_s[4];
    __shared__ float alpha_s;

    const float* src = (j == 0) ? cells_in : ((j & 1) ? g_buf0 : g_buf1);
    float*       dst = (j & 1) ? g_buf1 : g_buf0;

    const int tid  = threadIdx.x;
    const int brow = blockIdx.x >> 7;          // batch row (128 tiles per row)
    const int t0   = (blockIdx.x & 127) << 6;  // first token of tile
    const float* rowbase = src + (size_t)brow * TT * D_MODEL;

    if (tid < 4)  rw_s[tid] = g_rw[tid];
    if (tid == 4) alpha_s   = g_alpha;

    // load halo'd cell tile: tokens t0-1 .. t0+64 (66 x 64 floats), T wraps (roll)
    for (int i = tid; i < 66*16; i += 256){
        int tok = i >> 4, c4 = i & 15;
        int t = (t0 - 1 + tok) & (TT - 1);
        ((float4*)x_s)[i] = ((const float4*)(rowbase + (size_t)t * D_MODEL))[c4];
    }
    __syncthreads();

    const int nt  = tid & 31, mt  = tid >> 5;  // GEMM1: warp = 8-token group, lane = 4 cols
    const int nt2 = tid & 15, mt2 = tid >> 4;  // GEMM2/output: 4 tokens x 4 cols
    float outa[4][4] = {};

    for (int r = 0; r < NRULES; r++){
        // stage rule weights into smem
        {
            const float4* w1g = (const float4*)(rw1 + (size_t)r * K1 * HID);
            #pragma unroll 4
            for (int i = tid; i < (K1*HID)/4; i += 256) ((float4*)w1s)[i] = w1g[i];
            const float4* w2g = (const float4*)(rw2 + (size_t)r * HID * D_MODEL);
            #pragma unroll 2
            for (int i = tid; i < (HID*D_MODEL)/4; i += 256) ((float4*)w2s)[i] = w2g[i];
            if (tid < HID)                       b1s[tid]       = rb1[r*HID + tid];
            else if (tid < HID + D_MODEL)        b2s[tid - HID] = rb2[r*D_MODEL + tid - HID];
        }
        __syncthreads();

        // ---- GEMM1: h[64][128] = gelu(x3[64][192] @ W1 + b1)
        // x3 k-segments: [0,64)=cells[t], [64,128)=cells[t-1], [128,192)=cells[t+1]
        ull acc[8][2];
        #pragma unroll
        for (int a = 0; a < 8; a++){ acc[a][0] = 0ULL; acc[a][1] = 0ULL; }

        #pragma unroll
        for (int seg = 0; seg < 3; seg++){
            const int soff = (seg == 0) ? 1 : ((seg == 1) ? 0 : 2); // halo offset
            const float* xb = x_s + (8*mt + soff) * 64;
            const float* wb = w1s + seg*64*HID + 4*nt;
            #pragma unroll 2
            for (int kk = 0; kk < 64; kk++){
                ulonglong2 bw = *(const ulonglong2*)(wb + (size_t)kk*HID); // 4 weights = 2 f32x2 pairs
                #pragma unroll
                for (int mi = 0; mi < 8; mi++){
                    ull ap = dup2(xb[mi*64 + kk]);    // broadcast A (same addr all lanes)
                    acc[mi][0] = fma2(ap, bw.x, acc[mi][0]);
                    acc[mi][1] = fma2(ap, bw.y, acc[mi][1]);
                }
            }
        }
        {
            float bb0 = b1s[4*nt], bb1 = b1s[4*nt+1], bb2v = b1s[4*nt+2], bb3 = b1s[4*nt+3];
            #pragma unroll
            for (int mi = 0; mi < 8; mi++){
                float2 p0 = unp2(acc[mi][0]), p1 = unp2(acc[mi][1]);
                float4 hv;
                hv.x = gelu_exact(p0.x + bb0);
                hv.y = gelu_exact(p0.y + bb1);
                hv.z = gelu_exact(p1.x + bb2v);
                hv.w = gelu_exact(p1.y + bb3);
                *(float4*)(h_s + (size_t)(8*mt+mi)*HPITCH + 4*nt) = hv;
            }
        }
        __syncthreads();

        // ---- GEMM2: pre[64][64] = h @ W2 ; outa += rw[r]*tanh(pre + b2)
        ull acc2[4][2];
        #pragma unroll
        for (int a = 0; a < 4; a++){ acc2[a][0] = 0ULL; acc2[a][1] = 0ULL; }
        const float* hb  = h_s + (size_t)(4*mt2) * HPITCH;
        const float* w2b = w2s + 4*nt2;
        #pragma unroll 2
        for (int k = 0; k < HID; k++){
            ulonglong2 bw = *(const ulonglong2*)(w2b + (size_t)k*D_MODEL);
            #pragma unroll
            for (int mi = 0; mi < 4; mi++){
                ull ap = dup2(hb[(size_t)mi*HPITCH + k]);
                acc2[mi][0] = fma2(ap, bw.x, acc2[mi][0]);
                acc2[mi][1] = fma2(ap, bw.y, acc2[mi][1]);
            }
        }
        {
            float rr = rw_s[r];
            float c0 = b2s[4*nt2], c1 = b2s[4*nt2+1], c2v = b2s[4*nt2+2], c3 = b2s[4*nt2+3];
            #pragma unroll
            for (int mi = 0; mi < 4; mi++){
                float2 p0 = unp2(acc2[mi][0]), p1 = unp2(acc2[mi][1]);
                outa[mi][0] += rr * tanhf(p0.x + c0);
                outa[mi][1] += rr * tanhf(p0.y + c1);
                outa[mi][2] += rr * tanhf(p1.x + c2v);
                outa[mi][3] += rr * tanhf(p1.y + c3);
            }
        }
        __syncthreads();  // protect smem before next rule's weight staging
    }

    // cells = alpha*cells + (1-alpha)*new_cells
    const float al = alpha_s, om = 1.0f - al;
    float* drow = dst + ((size_t)brow*TT + t0) * D_MODEL;
    #pragma unroll
    for (int mi = 0; mi < 4; mi++){
        int m = 4*mt2 + mi;
        float4 cv = *(const float4*)(x_s + (size_t)(m+1)*64 + 4*nt2);
        float4 ov;
        ov.x = al*cv.x + om*outa[mi][0];
        ov.y = al*cv.y + om*outa[mi][1];
        ov.z = al*cv.z + om*outa[mi][2];
        ov.w = al*cv.w + om*outa[mi][3];
        *(float4*)(drow + (size_t)m*D_MODEL + 4*nt2) = ov;
    }
}

// ---------------- final LayerNorm ----------------
__global__ void __launch_bounds__(256)
ln_kernel(const float* __restrict__ g, const float* __restrict__ b,
          float* __restrict__ out)
{
    const float* src = ((g_nev - 1) & 1) ? g_buf1 : g_buf0;
    int tok  = blockIdx.x * 8 + (threadIdx.x >> 5);
    int lane = threadIdx.x & 31;
    const float2* p = (const float2*)(src + (size_t)tok * D_MODEL);
    float2 v = p[lane];

    float s = v.x + v.y;
    #pragma unroll
    for (int o = 16; o; o >>= 1) s += __shfl_xor_sync(0xffffffffu, s, o);
    float mu = s * (1.0f/64.0f);

    float dx = v.x - mu, dy = v.y - mu;
    float ss = dx*dx + dy*dy;
    #pragma unroll
    for (int o = 16; o; o >>= 1) ss += __shfl_xor_sync(0xffffffffu, ss, o);
    float rstd = rsqrtf(ss * (1.0f/64.0f) + LN_EPS);

    float2 gg = ((const float2*)g)[lane];
    float2 bb = ((const float2*)b)[lane];
    float2 ov;
    ov.x = dx * rstd * gg.x + bb.x;
    ov.y = dy * rstd * gg.y + bb.y;
    ((float2*)(out + (size_t)tok * D_MODEL))[lane] = ov;
}

// ---------------- launch ----------------
extern "C" void kernel_launch(void* const* d_in, const int* in_sizes, int n_in,
                              void* d_out, int out_size)
{
    const float* cells   = (const float*)d_in[0];
    const float* c_state = (const float*)d_in[1];
    const float* rule_w1 = (const float*)d_in[2];
    const float* rule_b1 = (const float*)d_in[3];
    const float* rule_w2 = (const float*)d_in[4];
    const float* rule_b2 = (const float*)d_in[5];
    const float* sel_w1  = (const float*)d_in[6];
    const float* sel_b1  = (const float*)d_in[7];
    const float* sel_w2  = (const float*)d_in[8];
    const float* sel_b2  = (const float*)d_in[9];
    const float* st_w1   = (const float*)d_in[10];
    const float* st_b1   = (const float*)d_in[11];
    const float* st_w2   = (const float*)d_in[12];
    const float* st_b2   = (const float*)d_in[13];
    const float* res_w1  = (const float*)d_in[14];
    const float* res_b1  = (const float*)d_in[15];
    const float* res_w2  = (const float*)d_in[16];
    const float* res_b2  = (const float*)d_in[17];
    const float* ln_g    = (const float*)d_in[18];
    const float* ln_b    = (const float*)d_in[19];

    cudaFuncSetAttribute(step_kernel,
                         cudaFuncAttributeMaxDynamicSharedMemorySize, SMEM_BYTES);

    control_kernel<<<1, 128>>>(c_state,
                               sel_w1, sel_b1, sel_w2, sel_b2,
                               st_w1,  st_b1,  st_w2,  st_b2,
                               res_w1, res_b1, res_w2, res_b2);

    for (int j = 0; j < 8; j++)
        step_kernel<<<NBLK, 256, SMEM_BYTES>>>(cells, rule_w1, rule_b1,
                                               rule_w2, rule_b2, j);

    ln_kernel<<<NTOK/8, 256>>>(ln_g, ln_b, (float*)d_out);
}

// round 2
// speedup vs baseline: 1.1237x; 1.1237x over previous
#include <cuda_runtime.h>
#include <cstdint>
#include <math.h>

// ---------------- problem constants ----------------
#define D_MODEL 64
#define HID     128
#define NRULES  4
#define K1      192              // 3*D_MODEL
#define BB      32
#define TT      8192
#define NTOK    (BB*TT)          // 262144
#define TILE    128              // tokens per block
#define NBLK    (NTOK/TILE)      // 2048
#define LN_EPS  1e-5f

// ---------------- smem layout (floats) ----------------
#define OFF_X   0
#define SZ_X    (130*64)         // halo tile: tokens t0-1 .. t0+128
#define OFF_W1  (OFF_X + SZ_X)
#define SZ_W1   (K1*HID)         // 192x128 = 24576
#define OFF_W2  (OFF_W1 + SZ_W1)
#define SZ_W2   (HID*D_MODEL)    // 128x64 = 8192
#define HPITCH  132              // padded pitch for h
#define OFF_H   (OFF_W2 + SZ_W2)
#define SZ_H    (128*HPITCH)     // 16896
#define SMEM_FLOATS (OFF_H + SZ_H)         // 57984
#define SMEM_BYTES  (SMEM_FLOATS*4)        // 231936 B (< 232448 limit)

// ---------------- device state (no allocations allowed) ----------------
__device__ float g_rw[4];
__device__ float g_alpha;
__device__ int   g_nev;
__device__ float g_buf0[(size_t)NTOK*D_MODEL];
__device__ float g_buf1[(size_t)NTOK*D_MODEL];

// ---------------- packed f32x2 helpers (full-rate FMA on sm_10x) ----------------
typedef unsigned long long ull;

__device__ __forceinline__ ull fma2(ull a, ull b, ull c){
    ull d; asm("fma.rn.f32x2 %0, %1, %2, %3;" : "=l"(d) : "l"(a), "l"(b), "l"(c)); return d;
}
__device__ __forceinline__ ull dup2(float a){
    ull d; asm("mov.b64 %0, {%1, %2};" : "=l"(d) : "f"(a), "f"(a)); return d;
}
__device__ __forceinline__ float2 unp2(ull v){
    float2 r; asm("mov.b64 {%0, %1}, %2;" : "=f"(r.x), "=f"(r.y) : "l"(v)); return r;
}

__device__ __forceinline__ float gelu_exact(float x){
    return 0.5f * x * (1.0f + erff(x * 0.7071067811865475f));
}

// ---------------- control kernel: rule_weights, n_evolve, alpha ----------------
__global__ void control_kernel(
    const float* __restrict__ c,
    const float* __restrict__ p_sw1, const float* __restrict__ p_sb1,
    const float* __restrict__ p_sw2, const float* __restrict__ p_sb2,
    const float* __restrict__ p_tw1, const float* __restrict__ p_tb1,
    const float* __restrict__ p_tw2, const float* __restrict__ p_tb2,
    const float* __restrict__ p_rw1, const float* __restrict__ p_rb1,
    const float* __restrict__ p_rw2, const float* __restrict__ p_rb2)
{
    __shared__ float cs[128];
    __shared__ float h1[64];
    __shared__ float h2[32];
    __shared__ float h3[32];
    int t = threadIdx.x;
    if (t < 128) cs[t] = c[t];
    __syncthreads();

    if (t < 64){
        float a = p_sb1[t];
        for (int k = 0; k < 128; k++) a += cs[k] * p_sw1[k*64 + t];
        h1[t] = gelu_exact(a);
    } else if (t < 96){
        int i = t - 64;
        float a = p_tb1[i];
        for (int k = 0; k < 128; k++) a += cs[k] * p_tw1[k*32 + i];
        h2[i] = gelu_exact(a);
    } else {
        int i = t - 96;
        float a = p_rb1[i];
        for (int k = 0; k < 128; k++) a += cs[k] * p_rw1[k*32 + i];
        h3[i] = gelu_exact(a);
    }
    __syncthreads();

    if (t == 0){
        float l[4]; float mx = -1e30f;
        for (int r = 0; r < 4; r++){
            float a = p_sb2[r];
            for (int i = 0; i < 64; i++) a += h1[i] * p_sw2[i*4 + r];
            l[r] = a; mx = fmaxf(mx, a);
        }
        float s = 0.0f;
        for (int r = 0; r < 4; r++){ l[r] = expf(l[r] - mx); s += l[r]; }
        for (int r = 0; r < 4; r++) g_rw[r] = l[r] / s;
    }
    if (t == 1){
        float l[7]; float mx = -1e30f;
        for (int jj = 0; jj < 7; jj++){
            float a = p_tb2[jj];
            for (int i = 0; i < 32; i++) a += h2[i] * p_tw2[i*7 + jj];
            l[jj] = a; mx = fmaxf(mx, a);
        }
        float s = 0.0f;
        for (int jj = 0; jj < 7; jj++){ l[jj] = expf(l[jj] - mx); s += l[jj]; }
        const float steps[7] = {2.0f,3.0f,4.0f,5.0f,6.0f,7.0f,8.0f};
        float nf = 0.0f;
        for (int jj = 0; jj < 7; jj++) nf += (l[jj] / s) * steps[jj];
        int n = (int)(nf + 0.5f);
        if (n < 2) n = 2;
        if (n > 8) n = 8;
        g_nev = n;
    }
    if (t == 2){
        float v = p_rb2[0];
        for (int i = 0; i < 32; i++) v += h3[i] * p_rw2[i];
        g_alpha = 0.1f + 0.8f / (1.0f + expf(-v));
    }
}

// ---------------- evolve step ----------------
__global__ void __launch_bounds__(256, 1)
step_kernel(const float* __restrict__ cells_in,
            const float* __restrict__ rw1, const float* __restrict__ rb1,
            const float* __restrict__ rw2, const float* __restrict__ rb2,
            int j)
{
    if (j >= g_nev) return;

    extern __shared__ float sm[];
    float* x_s  = sm + OFF_X;
    float* w1s  = sm + OFF_W1;
    float* w2s  = sm + OFF_W2;
    float* h_s  = sm + OFF_H;
    __shared__ float rw_s[4];
    __shared__ float alpha_s;

    const float* src = (j == 0) ? cells_in : ((j & 1) ? g_buf0 : g_buf1);
    float*       dst = (j & 1) ? g_buf1 : g_buf0;

    const int tid  = threadIdx.x;
    const int brow = blockIdx.x >> 6;          // batch row (64 tiles per row)
    const int t0   = (blockIdx.x & 63) << 7;   // first token of tile
    const float* rowbase = src + (size_t)brow * TT * D_MODEL;

    if (tid < 4)  rw_s[tid] = g_rw[tid];
    if (tid == 4) alpha_s   = g_alpha;

    // load halo'd cell tile: tokens t0-1 .. t0+128 (130 x 64 floats), T wraps
    for (int i = tid; i < 130*16; i += 256){
        int tok = i >> 4, c4 = i & 15;
        int t = (t0 - 1 + tok) & (TT - 1);
        ((float4*)x_s)[i] = ((const float4*)(rowbase + (size_t)t * D_MODEL))[c4];
    }

    // GEMM1 mapping: 16 token-groups (8 tokens) x 16 col-lanes (8 cols)
    const int n16 = tid & 15, mg = tid >> 4;
    // GEMM2 mapping: 32 token-groups (4 tokens) x 8 col-lanes (8 cols)
    const int n8 = tid & 7,  mg2 = tid >> 3;

    float outa[4][8];
    #pragma unroll
    for (int a = 0; a < 4; a++)
        #pragma unroll
        for (int b = 0; b < 8; b++) outa[a][b] = 0.0f;

    for (int r = 0; r < NRULES; r++){
        // stage rule weights into smem
        {
            const float4* w1g = (const float4*)(rw1 + (size_t)r * K1 * HID);
            #pragma unroll 4
            for (int i = tid; i < (K1*HID)/4; i += 256) ((float4*)w1s)[i] = w1g[i];
            const float4* w2g = (const float4*)(rw2 + (size_t)r * HID * D_MODEL);
            #pragma unroll 2
            for (int i = tid; i < (HID*D_MODEL)/4; i += 256) ((float4*)w2s)[i] = w2g[i];
        }
        __syncthreads();

        // ---- GEMM1: h[128][128] = gelu(x3[128][192] @ W1 + b1)
        // per thread: m=8 tokens, n=8 cols (4 f32x2 pairs)
        ull acc[8][4];
        #pragma unroll
        for (int a = 0; a < 8; a++){
            #pragma unroll
            for (int b = 0; b < 4; b++) acc[a][b] = 0ULL;
        }

        #pragma unroll
        for (int seg = 0; seg < 3; seg++){
            const int soff = (seg == 0) ? 1 : ((seg == 1) ? 0 : 2);
            const float* xb = x_s + (8*mg + soff) * 64;
            const float* wb = w1s + seg*64*HID + 8*n16;
            for (int kk = 0; kk < 64; kk += 4){
                float4 av[8];
                #pragma unroll
                for (int mi = 0; mi < 8; mi++)
                    av[mi] = *(const float4*)(xb + mi*64 + kk);
                #pragma unroll
                for (int dk = 0; dk < 4; dk++){
                    ulonglong2 b0 = *(const ulonglong2*)(wb + (size_t)(kk+dk)*HID);
                    ulonglong2 b1 = *(const ulonglong2*)(wb + (size_t)(kk+dk)*HID + 4);
                    #pragma unroll
                    for (int mi = 0; mi < 8; mi++){
                        float a = (dk == 0) ? av[mi].x : (dk == 1) ? av[mi].y
                                : (dk == 2) ? av[mi].z : av[mi].w;
                        ull ap = dup2(a);
                        acc[mi][0] = fma2(ap, b0.x, acc[mi][0]);
                        acc[mi][1] = fma2(ap, b0.y, acc[mi][1]);
                        acc[mi][2] = fma2(ap, b1.x, acc[mi][2]);
                        acc[mi][3] = fma2(ap, b1.y, acc[mi][3]);
                    }
                }
            }
        }
        {
            const float4 blo = __ldg((const float4*)(rb1 + r*HID + 8*n16));
            const float4 bhi = __ldg((const float4*)(rb1 + r*HID + 8*n16 + 4));
            #pragma unroll
            for (int mi = 0; mi < 8; mi++){
                float2 p0 = unp2(acc[mi][0]), p1 = unp2(acc[mi][1]);
                float2 p2 = unp2(acc[mi][2]), p3 = unp2(acc[mi][3]);
                float4 h0, h1;
                h0.x = gelu_exact(p0.x + blo.x);
                h0.y = gelu_exact(p0.y + blo.y);
                h0.z = gelu_exact(p1.x + blo.z);
                h0.w = gelu_exact(p1.y + blo.w);
                h1.x = gelu_exact(p2.x + bhi.x);
                h1.y = gelu_exact(p2.y + bhi.y);
                h1.z = gelu_exact(p3.x + bhi.z);
                h1.w = gelu_exact(p3.y + bhi.w);
                float* hp = h_s + (size_t)(8*mg + mi)*HPITCH + 8*n16;
                *(float4*)hp       = h0;
                *(float4*)(hp + 4) = h1;
            }
        }
        __syncthreads();

        // ---- GEMM2: pre[128][64] = h @ W2 ; outa += rw[r]*tanh(pre + b2)
        // per thread: m=4 tokens, n=8 cols
        ull acc2[4][4];
        #pragma unroll
        for (int a = 0; a < 4; a++){
            #pragma unroll
            for (int b = 0; b < 4; b++) acc2[a][b] = 0ULL;
        }
        const float* hb  = h_s + (size_t)(4*mg2) * HPITCH;
        const float* wb2 = w2s + 8*n8;
        for (int kk = 0; kk < HID; kk += 4){
            float4 hv[4];
            #pragma unroll
            for (int mi = 0; mi < 4; mi++)
                hv[mi] = *(const float4*)(hb + (size_t)mi*HPITCH + kk);
            #pragma unroll
            for (int dk = 0; dk < 4; dk++){
                ulonglong2 b0 = *(const ulonglong2*)(wb2 + (size_t)(kk+dk)*D_MODEL);
                ulonglong2 b1 = *(const ulonglong2*)(wb2 + (size_t)(kk+dk)*D_MODEL + 4);
                #pragma unroll
                for (int mi = 0; mi < 4; mi++){
                    float a = (dk == 0) ? hv[mi].x : (dk == 1) ? hv[mi].y
                            : (dk == 2) ? hv[mi].z : hv[mi].w;
                    ull ap = dup2(a);
                    acc2[mi][0] = fma2(ap, b0.x, acc2[mi][0]);
                    acc2[mi][1] = fma2(ap, b0.y, acc2[mi][1]);
                    acc2[mi][2] = fma2(ap, b1.x, acc2[mi][2]);
                    acc2[mi][3] = fma2(ap, b1.y, acc2[mi][3]);
                }
            }
        }
        {
            const float4 clo = __ldg((const float4*)(rb2 + r*D_MODEL + 8*n8));
            const float4 chi = __ldg((const float4*)(rb2 + r*D_MODEL + 8*n8 + 4));
            const float rr = rw_s[r];
            #pragma unroll
            for (int mi = 0; mi < 4; mi++){
                float2 p0 = unp2(acc2[mi][0]), p1 = unp2(acc2[mi][1]);
                float2 p2 = unp2(acc2[mi][2]), p3 = unp2(acc2[mi][3]);
                outa[mi][0] += rr * tanhf(p0.x + clo.x);
                outa[mi][1] += rr * tanhf(p0.y + clo.y);
                outa[mi][2] += rr * tanhf(p1.x + clo.z);
                outa[mi][3] += rr * tanhf(p1.y + clo.w);
                outa[mi][4] += rr * tanhf(p2.x + chi.x);
                outa[mi][5] += rr * tanhf(p2.y + chi.y);
                outa[mi][6] += rr * tanhf(p3.x + chi.z);
                outa[mi][7] += rr * tanhf(p3.y + chi.w);
            }
        }
        __syncthreads();  // protect smem before next rule's staging
    }

    // cells = alpha*cells + (1-alpha)*new_cells
    const float al = alpha_s, om = 1.0f - al;
    float* drow = dst + ((size_t)brow*TT + t0) * D_MODEL;
    #pragma unroll
    for (int mi = 0; mi < 4; mi++){
        int m = 4*mg2 + mi;
        const float* xr = x_s + (size_t)(m + 1)*64 + 8*n8;
        float4 cv0 = *(const float4*)xr;
        float4 cv1 = *(const float4*)(xr + 4);
        float4 o0, o1;
        o0.x = al*cv0.x + om*outa[mi][0];
        o0.y = al*cv0.y + om*outa[mi][1];
        o0.z = al*cv0.z + om*outa[mi][2];
        o0.w = al*cv0.w + om*outa[mi][3];
        o1.x = al*cv1.x + om*outa[mi][4];
        o1.y = al*cv1.y + om*outa[mi][5];
        o1.z = al*cv1.z + om*outa[mi][6];
        o1.w = al*cv1.w + om*outa[mi][7];
        float* dp = drow + (size_t)m*D_MODEL + 8*n8;
        *(float4*)dp       = o0;
        *(float4*)(dp + 4) = o1;
    }
}

// ---------------- final LayerNorm ----------------
__global__ void __launch_bounds__(256)
ln_kernel(const float* __restrict__ g, const float* __restrict__ b,
          float* __restrict__ out)
{
    const float* src = ((g_nev - 1) & 1) ? g_buf1 : g_buf0;
    int tok  = blockIdx.x * 8 + (threadIdx.x >> 5);
    int lane = threadIdx.x & 31;
    const float2* p = (const float2*)(src + (size_t)tok * D_MODEL);
    float2 v = p[lane];

    float s = v.x + v.y;
    #pragma unroll
    for (int o = 16; o; o >>= 1) s += __shfl_xor_sync(0xffffffffu, s, o);
    float mu = s * (1.0f/64.0f);

    float dx = v.x - mu, dy = v.y - mu;
    float ss = dx*dx + dy*dy;
    #pragma unroll
    for (int o = 16; o; o >>= 1) ss += __shfl_xor_sync(0xffffffffu, ss, o);
    float rstd = rsqrtf(ss * (1.0f/64.0f) + LN_EPS);

    float2 gg = ((const float2*)g)[lane];
    float2 bb = ((const float2*)b)[lane];
    float2 ov;
    ov.x = dx * rstd * gg.x + bb.x;
    ov.y = dy * rstd * gg.y + bb.y;
    ((float2*)(out + (size_t)tok * D_MODEL))[lane] = ov;
}

// ---------------- launch ----------------
extern "C" void kernel_launch(void* const* d_in, const int* in_sizes, int n_in,
                              void* d_out, int out_size)
{
    const float* cells   = (const float*)d_in[0];
    const float* c_state = (const float*)d_in[1];
    const float* rule_w1 = (const float*)d_in[2];
    const float* rule_b1 = (const float*)d_in[3];
    const float* rule_w2 = (const float*)d_in[4];
    const float* rule_b2 = (const float*)d_in[5];
    const float* sel_w1  = (const float*)d_in[6];
    const float* sel_b1  = (const float*)d_in[7];
    const float* sel_w2  = (const float*)d_in[8];
    const float* sel_b2  = (const float*)d_in[9];
    const float* st_w1   = (const float*)d_in[10];
    const float* st_b1   = (const float*)d_in[11];
    const float* st_w2   = (const float*)d_in[12];
    const float* st_b2   = (const float*)d_in[13];
    const float* res_w1  = (const float*)d_in[14];
    const float* res_b1  = (const float*)d_in[15];
    const float* res_w2  = (const float*)d_in[16];
    const float* res_b2  = (const float*)d_in[17];
    const float* ln_g    = (const float*)d_in[18];
    const float* ln_b    = (const float*)d_in[19];

    cudaFuncSetAttribute(step_kernel,
                         cudaFuncAttributeMaxDynamicSharedMemorySize, SMEM_BYTES);

    control_kernel<<<1, 128>>>(c_state,
                               sel_w1, sel_b1, sel_w2, sel_b2,
                               st_w1,  st_b1,  st_w2,  st_b2,
                               res_w1, res_b1, res_w2, res_b2);

    for (int j = 0; j < 8; j++)
        step_kernel<<<NBLK, 256, SMEM_BYTES>>>(cells, rule_w1, rule_b1,
                                               rule_w2, rule_b2, j);

    ln_kernel<<<NTOK/8, 256>>>(ln_g, ln_b, (float*)d_out);
}